// round 14
// baseline (speedup 1.0000x reference)
#include <cuda_runtime.h>
#include <cuda_fp16.h>
#include <math.h>
#include <stdint.h>

// ---------------- scratch (device globals; no allocations allowed) -----------
// Everything single fp16 plane now (V-lo dropped; PV 1-term).
__device__ __half g_X[4096 * 2048];
__device__ __half g_Xq[4096 * 1536];
__device__ __half g_Cb[4096 * 512];
__device__ __half g_Q[4096 * 2048];
__device__ __half g_K[16 * 4096 * 128];                             // [h][row][d]
__device__ __half g_Vt[16 * 128 * 4096];                            // [h][d][row]
__device__ __half g_AO[4096 * 2048];

__device__ __half g_Wqd[1536 * 2048];
__device__ __half g_Wqu[2048 * 1536];
__device__ __half g_Wkvd[512 * 2048];
__device__ __half g_Wo[2048 * 2048];
__device__ __half g_kupT[16 * 128 * 512];
__device__ __half g_vupT[16 * 128 * 512];

// ---------------- prep kernels ------------------------------------------------
__global__ void conv_single4(const float* __restrict__ in, __half* __restrict__ out, int n4)
{
    int i = blockIdx.x * blockDim.x + threadIdx.x;
    if (i >= n4) return;
    float4 v = ((const float4*)in)[i];
    __half2 a = __halves2half2(__float2half_rn(v.x), __float2half_rn(v.y));
    __half2 b = __halves2half2(__float2half_rn(v.z), __float2half_rn(v.w));
    uint2 o;
    o.x = *(uint32_t*)&a; o.y = *(uint32_t*)&b;
    *(uint2*)(out + i * 4) = o;
}

// in: [Z][K][N] fp32 -> single fp16 plane [Z][N][K]
__global__ void conv_transpose1(const float* __restrict__ in, __half* __restrict__ out,
                                int Z, int K, int N)
{
    long i = (long)blockIdx.x * blockDim.x + threadIdx.x;
    long total = (long)Z * K * N;
    if (i >= total) return;
    int n = (int)(i % N);
    long t = i / N;
    int k = (int)(t % K);
    int z = (int)(t / K);
    out[((long)z * N + n) * K + k] = __float2half_rn(in[i]);
}

// ---------------- shared helpers ---------------------------------------------
__device__ __forceinline__ uint32_t su(const void* p) {
    return (uint32_t)__cvta_generic_to_shared(p);
}
__device__ __forceinline__ void ldsm4(uint32_t* r, uint32_t addr) {
    asm volatile("ldmatrix.sync.aligned.m8n8.x4.shared.b16 {%0,%1,%2,%3}, [%4];"
                 : "=r"(r[0]), "=r"(r[1]), "=r"(r[2]), "=r"(r[3]) : "r"(addr));
}
__device__ __forceinline__ void mma16816h(float* c, const uint32_t* a, const uint32_t* b) {
    asm volatile("mma.sync.aligned.m16n8k16.row.col.f32.f16.f16.f32 "
                 "{%0,%1,%2,%3}, {%4,%5,%6,%7}, {%8,%9}, {%0,%1,%2,%3};"
                 : "+f"(c[0]), "+f"(c[1]), "+f"(c[2]), "+f"(c[3])
                 : "r"(a[0]), "r"(a[1]), "r"(a[2]), "r"(a[3]), "r"(b[0]), "r"(b[1]));
}
__device__ __forceinline__ void cpa16(uint32_t dst, const void* src) {
    asm volatile("cp.async.cg.shared.global [%0], [%1], 16;" :: "r"(dst), "l"(src));
}
__device__ __forceinline__ uint32_t pack2h(__half a, __half b) {
    __half2 t = __halves2half2(a, b);
    return *(uint32_t*)&t;
}

// ---------------- fp16 1-term mma.sync GEMM (A single, B single) --------------
#define BM 128
#define BN 128
#define BK 32
#define LDSS 40
#define PLANE_ELE (128 * LDSS)
#define PLANE_BYTES (PLANE_ELE * 2)      // 10240
#define STAGE_BYTES (2 * PLANE_BYTES)    // 20480: A, B
#define NS 2
#define GEMM_SMEM (NS * STAGE_BYTES)     // 40960 -> 2 CTAs/SM

// EPI: 0 = fp32 C out; 1 = single fp16 plane out (with merged-N support)
template <int EPI>
__global__ __launch_bounds__(256, 2)
void gemm_tc(const __half* __restrict__ A, const __half* __restrict__ B,
             float* __restrict__ C, __half* __restrict__ O,
             int M, int N, int K, int lda, int ldc,
             const __half* __restrict__ B2, __half* __restrict__ O2,
             int nSplit, int ldc2)
{
    extern __shared__ __half smem[];

    const int tid = threadIdx.x;
    const int mBase = blockIdx.y * BM;
    int nBase = blockIdx.x * BN;

    const __half* BL;
    __half* OL;
    int ldcL = ldc;
    if (EPI == 1 && nBase >= nSplit) {
        BL = B2; OL = O2;
        nBase -= nSplit; ldcL = ldc2;
    } else {
        BL = B; OL = O;
    }

    const int ldRow = tid >> 1;
    const int ldCol = (tid & 1) * 16;
    const uint32_t stsB = (uint32_t)(ldRow * LDSS + ldCol) * 2;

    const int lane = tid & 31;
    const int wid = tid >> 5;
    const int wm = wid >> 2;
    const int wn = wid & 3;
    const int aRowL = wm * 64 + (lane & 15);
    const int aKL = ((lane >> 4) << 3);
    const int bRowL = wn * 32 + ((lane >> 4) << 3) + (lane & 7);
    const int bKL = ((lane >> 3) & 1) << 3;

    const uint32_t smemBase = su(smem);
    const int nt = K / BK;

    const __half* pA = A + (long)(mBase + ldRow) * lda + ldCol;
    const __half* pB = BL + (long)(nBase + ldRow) * K + ldCol;

    auto loadStage = [&](int s, int kt) {
        const uint32_t d = smemBase + s * STAGE_BYTES + stsB;
        const long off = (long)kt * BK;
        cpa16(d, pA + off); cpa16(d + 16, pA + off + 8);
        cpa16(d + PLANE_BYTES, pB + off); cpa16(d + PLANE_BYTES + 16, pB + off + 8);
    };

    float acc[4][4][4];
#pragma unroll
    for (int i = 0; i < 4; i++)
#pragma unroll
        for (int j = 0; j < 4; j++)
#pragma unroll
            for (int k = 0; k < 4; k++) acc[i][j][k] = 0.f;

    loadStage(0, 0);
    asm volatile("cp.async.commit_group;" ::: "memory");

    for (int kt = 0; kt < nt; kt++) {
        asm volatile("cp.async.wait_group 0;" ::: "memory");
        __syncthreads();

        if (kt + 1 < nt) {
            loadStage((kt + 1) & 1, kt + 1);
            asm volatile("cp.async.commit_group;" ::: "memory");
        }

        const uint32_t sA = smemBase + (kt & 1) * STAGE_BYTES;
        const uint32_t sB = sA + PLANE_BYTES;

#pragma unroll
        for (int ks = 0; ks < BK; ks += 16) {
            uint32_t Af[4][4];
#pragma unroll
            for (int mb = 0; mb < 4; mb++) {
                const uint32_t off = ((aRowL + mb * 16) * LDSS + aKL + ks) * 2;
                ldsm4(Af[mb], sA + off);
            }
            uint32_t Bf[4][2];
#pragma unroll
            for (int nb2 = 0; nb2 < 2; nb2++) {
                const uint32_t off = ((bRowL + nb2 * 16) * LDSS + bKL + ks) * 2;
                uint32_t rg[4];
                ldsm4(rg, sB + off);
                Bf[nb2 * 2][0] = rg[0]; Bf[nb2 * 2][1] = rg[1];
                Bf[nb2 * 2 + 1][0] = rg[2]; Bf[nb2 * 2 + 1][1] = rg[3];
            }
#pragma unroll
            for (int mb = 0; mb < 4; mb++)
#pragma unroll
                for (int nb = 0; nb < 4; nb++)
                    mma16816h(acc[mb][nb], Af[mb], Bf[nb]);
        }
        __syncthreads();
    }

#pragma unroll
    for (int mb = 0; mb < 4; mb++) {
        const int r = mBase + wm * 64 + mb * 16 + (lane >> 2);
#pragma unroll
        for (int nb = 0; nb < 4; nb++) {
            const int cc = nBase + wn * 32 + nb * 8 + (lane & 3) * 2;
            float v0 = acc[mb][nb][0], v1 = acc[mb][nb][1];
            float v2 = acc[mb][nb][2], v3 = acc[mb][nb][3];
            if (EPI == 0) {
                *(float2*)&C[(long)r * ldcL + cc] = make_float2(v0, v1);
                *(float2*)&C[(long)(r + 8) * ldcL + cc] = make_float2(v2, v3);
            } else {
                __half2 a = __halves2half2(__float2half_rn(v0), __float2half_rn(v1));
                __half2 b = __halves2half2(__float2half_rn(v2), __float2half_rn(v3));
                *(__half2*)&OL[(long)r * ldcL + cc] = a;
                *(__half2*)&OL[(long)(r + 8) * ldcL + cc] = b;
            }
        }
    }
}

// ---------------- fused K-up + V-up GEMM (homogeneous, 1024 CTAs) -------------
// bid < 512 : K[h] = C @ kupT[h]^T, single plane row-major [h][row][d]
// else      : V[h] = C @ vupT[h]^T, single plane TRANSPOSED [h][d][row]
__global__ __launch_bounds__(256, 2)
void gemm_kv(const __half* __restrict__ Cb,
             const __half* __restrict__ ku, __half* __restrict__ kOut,
             const __half* __restrict__ vu, __half* __restrict__ vtOut)
{
    extern __shared__ __half smem[];
    const int tid = threadIdx.x;
    const int bid = blockIdx.x;
    const bool isV = bid >= 512;
    const int t = bid & 511;
    const int h = t >> 5;
    const int mBase = (t & 31) * 128;

    const __half* Bp = (isV ? vu : ku) + (long)h * 128 * 512;
    __half* Op = isV ? (vtOut + (long)h * 128 * 4096) : (kOut + (long)h * 4096 * 128);
    const int ldc = isV ? 4096 : 128;

    const int ldRow = tid >> 1;
    const int ldCol = (tid & 1) * 16;
    const uint32_t stsB = (uint32_t)(ldRow * LDSS + ldCol) * 2;

    const int lane = tid & 31;
    const int wid = tid >> 5;
    const int wm = wid >> 2;
    const int wn = wid & 3;
    const int aRowL = wm * 64 + (lane & 15);
    const int aKL = ((lane >> 4) << 3);
    const int bRowL = wn * 32 + ((lane >> 4) << 3) + (lane & 7);
    const int bKL = ((lane >> 3) & 1) << 3;

    const uint32_t smemBase = su(smem);
    const int nt = 512 / BK;

    const __half* pA = Cb + (long)(mBase + ldRow) * 512 + ldCol;
    const __half* pB = Bp + (long)ldRow * 512 + ldCol;

    auto loadStage = [&](int s, int kt) {
        const uint32_t d = smemBase + s * STAGE_BYTES + stsB;
        const long off = (long)kt * BK;
        cpa16(d, pA + off); cpa16(d + 16, pA + off + 8);
        cpa16(d + PLANE_BYTES, pB + off); cpa16(d + PLANE_BYTES + 16, pB + off + 8);
    };

    float acc[4][4][4];
#pragma unroll
    for (int i = 0; i < 4; i++)
#pragma unroll
        for (int j = 0; j < 4; j++)
#pragma unroll
            for (int k = 0; k < 4; k++) acc[i][j][k] = 0.f;

    loadStage(0, 0);
    asm volatile("cp.async.commit_group;" ::: "memory");

    for (int kt = 0; kt < nt; kt++) {
        asm volatile("cp.async.wait_group 0;" ::: "memory");
        __syncthreads();

        if (kt + 1 < nt) {
            loadStage((kt + 1) & 1, kt + 1);
            asm volatile("cp.async.commit_group;" ::: "memory");
        }

        const uint32_t sA = smemBase + (kt & 1) * STAGE_BYTES;
        const uint32_t sB = sA + PLANE_BYTES;

#pragma unroll
        for (int ks = 0; ks < BK; ks += 16) {
            uint32_t Af[4][4];
#pragma unroll
            for (int mb = 0; mb < 4; mb++) {
                const uint32_t off = ((aRowL + mb * 16) * LDSS + aKL + ks) * 2;
                ldsm4(Af[mb], sA + off);
            }
            uint32_t Bf[4][2];
#pragma unroll
            for (int nb2 = 0; nb2 < 2; nb2++) {
                const uint32_t off = ((bRowL + nb2 * 16) * LDSS + bKL + ks) * 2;
                uint32_t rg[4];
                ldsm4(rg, sB + off);
                Bf[nb2 * 2][0] = rg[0]; Bf[nb2 * 2][1] = rg[1];
                Bf[nb2 * 2 + 1][0] = rg[2]; Bf[nb2 * 2 + 1][1] = rg[3];
            }
#pragma unroll
            for (int mb = 0; mb < 4; mb++)
#pragma unroll
                for (int nb = 0; nb < 4; nb++)
                    mma16816h(acc[mb][nb], Af[mb], Bf[nb]);
        }
        __syncthreads();
    }

#pragma unroll
    for (int mb = 0; mb < 4; mb++) {
        const int r = mBase + wm * 64 + mb * 16 + (lane >> 2);
#pragma unroll
        for (int nb = 0; nb < 4; nb++) {
            const int cc = wn * 32 + nb * 8 + (lane & 3) * 2;
            float v0 = acc[mb][nb][0], v1 = acc[mb][nb][1];
            float v2 = acc[mb][nb][2], v3 = acc[mb][nb][3];
            __half h0 = __float2half_rn(v0), h1 = __float2half_rn(v1);
            __half h2 = __float2half_rn(v2), h3 = __float2half_rn(v3);
            if (!isV) {
                *(__half2*)&Op[(long)r * ldc + cc] = __halves2half2(h0, h1);
                *(__half2*)&Op[(long)(r + 8) * ldc + cc] = __halves2half2(h2, h3);
            } else {
                Op[(long)cc * ldc + r] = h0;
                Op[(long)(cc + 1) * ldc + r] = h1;
                Op[(long)cc * ldc + r + 8] = h2;
                Op[(long)(cc + 1) * ldc + r + 8] = h3;
            }
        }
    }
}

// ---------------- fp16 flash attention: S 1-term, PV 1-term -------------------
#define FQ_S 136
#define FV_S 72
#define FQ_O 0
#define FK_O 17408             // + stage*8704 (K single plane)
#define FV_O 34816             // + stage*9216 (V single plane)
#define FLASH_SMEM ((34816 + 2 * 9216) * 2)   // 106496 bytes
#define SCALE_F 0.08838834764831845f

__global__ __launch_bounds__(256)
void flash_tc(const __half* __restrict__ Q,
              const __half* __restrict__ K,
              const __half* __restrict__ Vt,
              __half* __restrict__ AO)
{
    extern __shared__ __half fsm[];
    const int qt = (int)gridDim.x - 1 - (int)blockIdx.x;   // LPT
    const int h = blockIdx.y, b = blockIdx.z;
    const int tid = threadIdx.x, lane = tid & 31, w = tid >> 5;
    const float slope = exp2f(-0.5f * (float)(h + 1));
    const int nt = 2 * qt + 2;

    const uint32_t fb = su(fsm);

    {
        const int r = tid >> 1, cb = (tid & 1) * 64;
        const __half* sq = Q + (long)(b * 2048 + qt * 128 + r) * 2048 + h * 128 + cb;
        const uint32_t dq = fb + (FQ_O + r * FQ_S + cb) * 2;
#pragma unroll
        for (int u = 0; u < 8; u++) cpa16(dq + u * 16, sq + u * 8);
    }
    auto loadKV = [&](int stg, int jt) {
        const int kr = tid >> 2, kcb = (tid & 3) * 32;
        const long krow = (long)h * 4096 + b * 2048 + jt * 64 + kr;
        const __half* sk = K + krow * 128 + kcb;
        const uint32_t kd = fb + (FK_O + stg * 8704 + kr * FQ_S + kcb) * 2;
#pragma unroll
        for (int u = 0; u < 4; u++) cpa16(kd + u * 16, sk + u * 8);
        const int vr = tid >> 1, vcb = (tid & 1) * 32;
        const long vrow = (long)h * 128 + vr;
        const __half* sv = Vt + vrow * 4096 + b * 2048 + jt * 64 + vcb;
        const uint32_t vd = fb + (FV_O + stg * 9216 + vr * FV_S + vcb) * 2;
#pragma unroll
        for (int u = 0; u < 4; u++) cpa16(vd + u * 16, sv + u * 8);
    };
    loadKV(0, 0);
    asm volatile("cp.async.commit_group;");

    const int aRow = w * 16 + (lane & 15);
    const int aCol8 = (lane >> 4) << 3;
    const int bRow8 = ((lane >> 4) << 3) + (lane & 7);
    const int bCol8 = ((lane >> 3) & 1) << 3;

    float m0 = -1e30f, m1 = -1e30f, l0 = 0.f, l1 = 0.f;
    float o[16][4];
#pragma unroll
    for (int i = 0; i < 16; i++)
#pragma unroll
        for (int j = 0; j < 4; j++) o[i][j] = 0.f;

    const int grow0 = qt * 128 + w * 16 + (lane >> 2);

    for (int jt = 0; jt < nt; jt++) {
        const int cur = jt & 1;
        if (jt > 0) __syncthreads();
        if (jt + 1 < nt) {
            loadKV(cur ^ 1, jt + 1);
            asm volatile("cp.async.commit_group;");
            asm volatile("cp.async.wait_group 1;");
        } else {
            asm volatile("cp.async.wait_group 0;");
        }
        __syncthreads();

        const uint32_t bK = fb + (FK_O + cur * 8704) * 2;
        const uint32_t bV = fb + (FV_O + cur * 9216) * 2;

        float s[8][4];
#pragma unroll
        for (int i = 0; i < 8; i++)
#pragma unroll
            for (int j = 0; j < 4; j++) s[i][j] = 0.f;

#pragma unroll
        for (int ks = 0; ks < 8; ks++) {
            uint32_t qf[4];
            const uint32_t aoff = (uint32_t)(aRow * FQ_S + ks * 16 + aCol8) * 2;
            ldsm4(qf, fb + FQ_O * 2 + aoff);
#pragma unroll
            for (int nb2 = 0; nb2 < 4; nb2++) {
                const uint32_t boff = (uint32_t)((nb2 * 16 + bRow8) * FQ_S + ks * 16 + bCol8) * 2;
                uint32_t kk[4];
                ldsm4(kk, bK + boff);
                mma16816h(s[2 * nb2],     qf, &kk[0]);
                mma16816h(s[2 * nb2 + 1], qf, &kk[2]);
            }
        }

#pragma unroll
        for (int nb = 0; nb < 8; nb++) {
#pragma unroll
            for (int j = 0; j < 2; j++) {
                const int gc = jt * 64 + nb * 8 + (lane & 3) * 2 + j;
                float v = s[nb][j];
                s[nb][j] = (gc > grow0) ? -1e30f
                          : v * SCALE_F - slope * (float)(grow0 - gc);
                float v2 = s[nb][2 + j];
                s[nb][2 + j] = (gc > grow0 + 8) ? -1e30f
                          : v2 * SCALE_F - slope * (float)(grow0 + 8 - gc);
            }
        }

        float mx0 = -1e30f, mx1 = -1e30f;
#pragma unroll
        for (int nb = 0; nb < 8; nb++) {
            mx0 = fmaxf(mx0, fmaxf(s[nb][0], s[nb][1]));
            mx1 = fmaxf(mx1, fmaxf(s[nb][2], s[nb][3]));
        }
        mx0 = fmaxf(mx0, __shfl_xor_sync(0xffffffffu, mx0, 1));
        mx0 = fmaxf(mx0, __shfl_xor_sync(0xffffffffu, mx0, 2));
        mx1 = fmaxf(mx1, __shfl_xor_sync(0xffffffffu, mx1, 1));
        mx1 = fmaxf(mx1, __shfl_xor_sync(0xffffffffu, mx1, 2));
        const float mn0 = fmaxf(m0, mx0), mn1 = fmaxf(m1, mx1);
        const float al0 = __expf(m0 - mn0), al1 = __expf(m1 - mn1);
        m0 = mn0; m1 = mn1;

        float sum0 = 0.f, sum1 = 0.f;
#pragma unroll
        for (int nb = 0; nb < 8; nb++) {
            s[nb][0] = __half2float(__float2half_rn(__expf(s[nb][0] - mn0))); sum0 += s[nb][0];
            s[nb][1] = __half2float(__float2half_rn(__expf(s[nb][1] - mn0))); sum0 += s[nb][1];
            s[nb][2] = __half2float(__float2half_rn(__expf(s[nb][2] - mn1))); sum1 += s[nb][2];
            s[nb][3] = __half2float(__float2half_rn(__expf(s[nb][3] - mn1))); sum1 += s[nb][3];
        }
        sum0 += __shfl_xor_sync(0xffffffffu, sum0, 1);
        sum0 += __shfl_xor_sync(0xffffffffu, sum0, 2);
        sum1 += __shfl_xor_sync(0xffffffffu, sum1, 1);
        sum1 += __shfl_xor_sync(0xffffffffu, sum1, 2);
        l0 = l0 * al0 + sum0;
        l1 = l1 * al1 + sum1;

#pragma unroll
        for (int nb = 0; nb < 16; nb++) {
            o[nb][0] *= al0; o[nb][1] *= al0;
            o[nb][2] *= al1; o[nb][3] *= al1;
        }

        uint32_t ph[4][4];
#pragma unroll
        for (int kb = 0; kb < 4; kb++) {
#pragma unroll
            for (int q = 0; q < 4; q++) {
                const float x = s[2 * kb + (q >> 1)][(q & 1) * 2 + 0];
                const float y = s[2 * kb + (q >> 1)][(q & 1) * 2 + 1];
                ph[kb][q] = pack2h(__float2half_rn(x), __float2half_rn(y));
            }
        }

#pragma unroll
        for (int kb = 0; kb < 4; kb++) {
#pragma unroll
            for (int nb2 = 0; nb2 < 8; nb2++) {
                const uint32_t voff = (uint32_t)((nb2 * 16 + bRow8) * FV_S + kb * 16 + bCol8) * 2;
                uint32_t vv[4];
                ldsm4(vv, bV + voff);
                mma16816h(o[2 * nb2],     ph[kb], &vv[0]);
                mma16816h(o[2 * nb2 + 1], ph[kb], &vv[2]);
            }
        }
    }

    const float inv0 = 1.f / l0, inv1 = 1.f / l1;
    const long row0 = (long)b * 2048 + qt * 128 + w * 16 + (lane >> 2);
#pragma unroll
    for (int nb = 0; nb < 16; nb++) {
        const int c = h * 128 + nb * 8 + (lane & 3) * 2;
        *(__half2*)&AO[row0 * 2048 + c] =
            __halves2half2(__float2half_rn(o[nb][0] * inv0), __float2half_rn(o[nb][1] * inv0));
        *(__half2*)&AO[(row0 + 8) * 2048 + c] =
            __halves2half2(__float2half_rn(o[nb][2] * inv1), __float2half_rn(o[nb][3] * inv1));
    }
}

// ---------------- launch ------------------------------------------------------
extern "C" void kernel_launch(void* const* d_in, const int* in_sizes, int n_in,
                              void* d_out, int out_size)
{
    const float* X    = (const float*)d_in[0];
    const float* Wqd  = (const float*)d_in[1];
    const float* Wqu  = (const float*)d_in[2];
    const float* Wkvd = (const float*)d_in[3];
    const float* kup  = (const float*)d_in[4];
    const float* vup  = (const float*)d_in[5];
    const float* Wo   = (const float*)d_in[6];
    float* out = (float*)d_out;

    __half *x, *xq, *cb, *q, *k, *vt, *ao;
    cudaGetSymbolAddress((void**)&x, g_X);
    cudaGetSymbolAddress((void**)&xq, g_Xq);
    cudaGetSymbolAddress((void**)&cb, g_Cb);
    cudaGetSymbolAddress((void**)&q, g_Q);
    cudaGetSymbolAddress((void**)&k, g_K);
    cudaGetSymbolAddress((void**)&vt, g_Vt);
    cudaGetSymbolAddress((void**)&ao, g_AO);

    __half *wqd, *wqu, *wkvd, *wo, *ku, *vu;
    cudaGetSymbolAddress((void**)&wqd, g_Wqd);
    cudaGetSymbolAddress((void**)&wqu, g_Wqu);
    cudaGetSymbolAddress((void**)&wkvd, g_Wkvd);
    cudaGetSymbolAddress((void**)&wo, g_Wo);
    cudaGetSymbolAddress((void**)&ku, g_kupT);
    cudaGetSymbolAddress((void**)&vu, g_vupT);

    cudaFuncSetAttribute(gemm_tc<0>, cudaFuncAttributeMaxDynamicSharedMemorySize, GEMM_SMEM);
    cudaFuncSetAttribute(gemm_tc<1>, cudaFuncAttributeMaxDynamicSharedMemorySize, GEMM_SMEM);
    cudaFuncSetAttribute(gemm_kv, cudaFuncAttributeMaxDynamicSharedMemorySize, GEMM_SMEM);
    cudaFuncSetAttribute(flash_tc, cudaFuncAttributeMaxDynamicSharedMemorySize, FLASH_SMEM);

    // ---- prep: single fp16 planes everywhere ----
    conv_single4<<<(4096 * 2048 / 4 + 255) / 256, 256>>>(X, x, 4096 * 2048 / 4);
    conv_single4<<<(1536 * 2048 / 4 + 255) / 256, 256>>>(Wqd, wqd, 1536 * 2048 / 4);
    conv_single4<<<(2048 * 1536 / 4 + 255) / 256, 256>>>(Wqu, wqu, 2048 * 1536 / 4);
    conv_single4<<<(512 * 2048 / 4 + 255) / 256, 256>>>(Wkvd, wkvd, 512 * 2048 / 4);
    conv_single4<<<(2048 * 2048 / 4 + 255) / 256, 256>>>(Wo, wo, 2048 * 2048 / 4);
    conv_transpose1<<<(16 * 512 * 128 + 255) / 256, 256>>>(kup, ku, 16, 512, 128);
    conv_transpose1<<<(16 * 512 * 128 + 255) / 256, 256>>>(vup, vu, 16, 512, 128);

    // 1) [Xq | C] = X @ [Wqd | Wkvd]^T  (merged-N)
    gemm_tc<1><<<dim3(16, 32), 256, GEMM_SMEM>>>(x, wqd, nullptr, xq,
        4096, 2048, 2048, 2048, 1536,
        wkvd, cb, 1536, 512);
    // 2) Q = Xq @ Wq_up^T
    gemm_tc<1><<<dim3(16, 32), 256, GEMM_SMEM>>>(xq, wqu, nullptr, q,
        4096, 2048, 1536, 1536, 2048,
        nullptr, nullptr, 1 << 30, 0);
    // 3) fused K/V up-projections (both single plane; V transposed)
    gemm_kv<<<1024, 256, GEMM_SMEM>>>(cb, ku, k, vu, vt);
    // 4) attention (LPT; S and PV both 1-term)
    flash_tc<<<dim3(16, 16, 2), 256, FLASH_SMEM>>>(q, k, vt, ao);
    // 5) out = AO @ Wo^T (fp32)
    gemm_tc<0><<<dim3(16, 32), 256, GEMM_SMEM>>>(ao, wo, out, nullptr,
        4096, 2048, 2048, 2048, 2048,
        nullptr, nullptr, 1 << 30, 0);
}

// round 16
// speedup vs baseline: 1.5208x; 1.5208x over previous
#include <cuda_runtime.h>
#include <cuda_fp16.h>
#include <math.h>
#include <stdint.h>

// ---------------- scratch (device globals; no allocations allowed) -----------
// Everything single fp16 plane (V-lo dropped; PV 1-term).
__device__ __half g_X[4096 * 2048];
__device__ __half g_Xq[4096 * 1536];
__device__ __half g_Cb[4096 * 512];
__device__ __half g_Q[4096 * 2048];
__device__ __half g_K[16 * 4096 * 128];                             // [h][row][d]
__device__ __half g_Vt[16 * 128 * 4096];                            // [h][d][row]
__device__ __half g_AO[4096 * 2048];

__device__ __half g_Wqd[1536 * 2048];
__device__ __half g_Wqu[2048 * 1536];
__device__ __half g_Wkvd[512 * 2048];
__device__ __half g_Wo[2048 * 2048];
__device__ __half g_kupT[16 * 128 * 512];
__device__ __half g_vupT[16 * 128 * 512];

// ---------------- prep kernels ------------------------------------------------
__global__ void conv_single4(const float* __restrict__ in, __half* __restrict__ out, int n4)
{
    int i = blockIdx.x * blockDim.x + threadIdx.x;
    if (i >= n4) return;
    float4 v = ((const float4*)in)[i];
    __half2 a = __halves2half2(__float2half_rn(v.x), __float2half_rn(v.y));
    __half2 b = __halves2half2(__float2half_rn(v.z), __float2half_rn(v.w));
    uint2 o;
    o.x = *(uint32_t*)&a; o.y = *(uint32_t*)&b;
    *(uint2*)(out + i * 4) = o;
}

// in: [Z][K][N] fp32 -> single fp16 plane [Z][N][K]
__global__ void conv_transpose1(const float* __restrict__ in, __half* __restrict__ out,
                                int Z, int K, int N)
{
    long i = (long)blockIdx.x * blockDim.x + threadIdx.x;
    long total = (long)Z * K * N;
    if (i >= total) return;
    int n = (int)(i % N);
    long t = i / N;
    int k = (int)(t % K);
    int z = (int)(t / K);
    out[((long)z * N + n) * K + k] = __float2half_rn(in[i]);
}

// ---------------- shared helpers ---------------------------------------------
__device__ __forceinline__ uint32_t su(const void* p) {
    return (uint32_t)__cvta_generic_to_shared(p);
}
__device__ __forceinline__ void ldsm4(uint32_t* r, uint32_t addr) {
    asm volatile("ldmatrix.sync.aligned.m8n8.x4.shared.b16 {%0,%1,%2,%3}, [%4];"
                 : "=r"(r[0]), "=r"(r[1]), "=r"(r[2]), "=r"(r[3]) : "r"(addr));
}
__device__ __forceinline__ void mma16816h(float* c, const uint32_t* a, const uint32_t* b) {
    asm volatile("mma.sync.aligned.m16n8k16.row.col.f32.f16.f16.f32 "
                 "{%0,%1,%2,%3}, {%4,%5,%6,%7}, {%8,%9}, {%0,%1,%2,%3};"
                 : "+f"(c[0]), "+f"(c[1]), "+f"(c[2]), "+f"(c[3])
                 : "r"(a[0]), "r"(a[1]), "r"(a[2]), "r"(a[3]), "r"(b[0]), "r"(b[1]));
}
__device__ __forceinline__ void cpa16(uint32_t dst, const void* src) {
    asm volatile("cp.async.cg.shared.global [%0], [%1], 16;" :: "r"(dst), "l"(src));
}
__device__ __forceinline__ uint32_t pack2h(__half a, __half b) {
    __half2 t = __halves2half2(a, b);
    return *(uint32_t*)&t;
}

// ---------------- fp16 1-term mma.sync GEMM (A single, B single) --------------
#define BM 128
#define BN 128
#define BK 32
#define LDSS 40
#define PLANE_ELE (128 * LDSS)
#define PLANE_BYTES (PLANE_ELE * 2)      // 10240
#define STAGE_BYTES (2 * PLANE_BYTES)    // 20480: A, B
#define NS 2
#define GEMM_SMEM (NS * STAGE_BYTES)     // 40960 -> 2 CTAs/SM

// EPI: 0 = fp32 C out; 1 = single fp16 plane out (with merged-N support)
template <int EPI>
__global__ __launch_bounds__(256, 2)
void gemm_tc(const __half* __restrict__ A, const __half* __restrict__ B,
             float* __restrict__ C, __half* __restrict__ O,
             int M, int N, int K, int lda, int ldc,
             const __half* __restrict__ B2, __half* __restrict__ O2,
             int nSplit, int ldc2)
{
    extern __shared__ __half smem[];

    const int tid = threadIdx.x;
    const int mBase = blockIdx.y * BM;
    int nBase = blockIdx.x * BN;

    const __half* BL;
    __half* OL;
    int ldcL = ldc;
    if (EPI == 1 && nBase >= nSplit) {
        BL = B2; OL = O2;
        nBase -= nSplit; ldcL = ldc2;
    } else {
        BL = B; OL = O;
    }

    const int ldRow = tid >> 1;
    const int ldCol = (tid & 1) * 16;
    const uint32_t stsB = (uint32_t)(ldRow * LDSS + ldCol) * 2;

    const int lane = tid & 31;
    const int wid = tid >> 5;
    const int wm = wid >> 2;
    const int wn = wid & 3;
    const int aRowL = wm * 64 + (lane & 15);
    const int aKL = ((lane >> 4) << 3);
    const int bRowL = wn * 32 + ((lane >> 4) << 3) + (lane & 7);
    const int bKL = ((lane >> 3) & 1) << 3;

    const uint32_t smemBase = su(smem);
    const int nt = K / BK;

    const __half* pA = A + (long)(mBase + ldRow) * lda + ldCol;
    const __half* pB = BL + (long)(nBase + ldRow) * K + ldCol;

    auto loadStage = [&](int s, int kt) {
        const uint32_t d = smemBase + s * STAGE_BYTES + stsB;
        const long off = (long)kt * BK;
        cpa16(d, pA + off); cpa16(d + 16, pA + off + 8);
        cpa16(d + PLANE_BYTES, pB + off); cpa16(d + PLANE_BYTES + 16, pB + off + 8);
    };

    float acc[4][4][4];
#pragma unroll
    for (int i = 0; i < 4; i++)
#pragma unroll
        for (int j = 0; j < 4; j++)
#pragma unroll
            for (int k = 0; k < 4; k++) acc[i][j][k] = 0.f;

    loadStage(0, 0);
    asm volatile("cp.async.commit_group;" ::: "memory");

    for (int kt = 0; kt < nt; kt++) {
        asm volatile("cp.async.wait_group 0;" ::: "memory");
        __syncthreads();

        if (kt + 1 < nt) {
            loadStage((kt + 1) & 1, kt + 1);
            asm volatile("cp.async.commit_group;" ::: "memory");
        }

        const uint32_t sA = smemBase + (kt & 1) * STAGE_BYTES;
        const uint32_t sB = sA + PLANE_BYTES;

#pragma unroll
        for (int ks = 0; ks < BK; ks += 16) {
            uint32_t Af[4][4];
#pragma unroll
            for (int mb = 0; mb < 4; mb++) {
                const uint32_t off = ((aRowL + mb * 16) * LDSS + aKL + ks) * 2;
                ldsm4(Af[mb], sA + off);
            }
            uint32_t Bf[4][2];
#pragma unroll
            for (int nb2 = 0; nb2 < 2; nb2++) {
                const uint32_t off = ((bRowL + nb2 * 16) * LDSS + bKL + ks) * 2;
                uint32_t rg[4];
                ldsm4(rg, sB + off);
                Bf[nb2 * 2][0] = rg[0]; Bf[nb2 * 2][1] = rg[1];
                Bf[nb2 * 2 + 1][0] = rg[2]; Bf[nb2 * 2 + 1][1] = rg[3];
            }
#pragma unroll
            for (int mb = 0; mb < 4; mb++)
#pragma unroll
                for (int nb = 0; nb < 4; nb++)
                    mma16816h(acc[mb][nb], Af[mb], Bf[nb]);
        }
        __syncthreads();
    }

#pragma unroll
    for (int mb = 0; mb < 4; mb++) {
        const int r = mBase + wm * 64 + mb * 16 + (lane >> 2);
#pragma unroll
        for (int nb = 0; nb < 4; nb++) {
            const int cc = nBase + wn * 32 + nb * 8 + (lane & 3) * 2;
            float v0 = acc[mb][nb][0], v1 = acc[mb][nb][1];
            float v2 = acc[mb][nb][2], v3 = acc[mb][nb][3];
            if (EPI == 0) {
                *(float2*)&C[(long)r * ldcL + cc] = make_float2(v0, v1);
                *(float2*)&C[(long)(r + 8) * ldcL + cc] = make_float2(v2, v3);
            } else {
                __half2 a = __halves2half2(__float2half_rn(v0), __float2half_rn(v1));
                __half2 b = __halves2half2(__float2half_rn(v2), __float2half_rn(v3));
                *(__half2*)&OL[(long)r * ldcL + cc] = a;
                *(__half2*)&OL[(long)(r + 8) * ldcL + cc] = b;
            }
        }
    }
}

// ---------------- fused K-up + V-up GEMM (homogeneous, 1024 CTAs) -------------
// bid < 512 : K[h] = C @ kupT[h]^T, single plane row-major [h][row][d]
// else      : V[h] = C @ vupT[h]^T, single plane TRANSPOSED [h][d][row]
__global__ __launch_bounds__(256, 2)
void gemm_kv(const __half* __restrict__ Cb,
             const __half* __restrict__ ku, __half* __restrict__ kOut,
             const __half* __restrict__ vu, __half* __restrict__ vtOut)
{
    extern __shared__ __half smem[];
    const int tid = threadIdx.x;
    const int bid = blockIdx.x;
    const bool isV = bid >= 512;
    const int t = bid & 511;
    const int h = t >> 5;
    const int mBase = (t & 31) * 128;

    const __half* Bp = (isV ? vu : ku) + (long)h * 128 * 512;
    __half* Op = isV ? (vtOut + (long)h * 128 * 4096) : (kOut + (long)h * 4096 * 128);
    const int ldc = isV ? 4096 : 128;

    const int ldRow = tid >> 1;
    const int ldCol = (tid & 1) * 16;
    const uint32_t stsB = (uint32_t)(ldRow * LDSS + ldCol) * 2;

    const int lane = tid & 31;
    const int wid = tid >> 5;
    const int wm = wid >> 2;
    const int wn = wid & 3;
    const int aRowL = wm * 64 + (lane & 15);
    const int aKL = ((lane >> 4) << 3);
    const int bRowL = wn * 32 + ((lane >> 4) << 3) + (lane & 7);
    const int bKL = ((lane >> 3) & 1) << 3;

    const uint32_t smemBase = su(smem);
    const int nt = 512 / BK;

    const __half* pA = Cb + (long)(mBase + ldRow) * 512 + ldCol;
    const __half* pB = Bp + (long)ldRow * 512 + ldCol;

    auto loadStage = [&](int s, int kt) {
        const uint32_t d = smemBase + s * STAGE_BYTES + stsB;
        const long off = (long)kt * BK;
        cpa16(d, pA + off); cpa16(d + 16, pA + off + 8);
        cpa16(d + PLANE_BYTES, pB + off); cpa16(d + PLANE_BYTES + 16, pB + off + 8);
    };

    float acc[4][4][4];
#pragma unroll
    for (int i = 0; i < 4; i++)
#pragma unroll
        for (int j = 0; j < 4; j++)
#pragma unroll
            for (int k = 0; k < 4; k++) acc[i][j][k] = 0.f;

    loadStage(0, 0);
    asm volatile("cp.async.commit_group;" ::: "memory");

    for (int kt = 0; kt < nt; kt++) {
        asm volatile("cp.async.wait_group 0;" ::: "memory");
        __syncthreads();

        if (kt + 1 < nt) {
            loadStage((kt + 1) & 1, kt + 1);
            asm volatile("cp.async.commit_group;" ::: "memory");
        }

        const uint32_t sA = smemBase + (kt & 1) * STAGE_BYTES;
        const uint32_t sB = sA + PLANE_BYTES;

#pragma unroll
        for (int ks = 0; ks < BK; ks += 16) {
            uint32_t Af[4][4];
#pragma unroll
            for (int mb = 0; mb < 4; mb++) {
                const uint32_t off = ((aRowL + mb * 16) * LDSS + aKL + ks) * 2;
                ldsm4(Af[mb], sA + off);
            }
            uint32_t Bf[4][2];
#pragma unroll
            for (int nb2 = 0; nb2 < 2; nb2++) {
                const uint32_t off = ((bRowL + nb2 * 16) * LDSS + bKL + ks) * 2;
                uint32_t rg[4];
                ldsm4(rg, sB + off);
                Bf[nb2 * 2][0] = rg[0]; Bf[nb2 * 2][1] = rg[1];
                Bf[nb2 * 2 + 1][0] = rg[2]; Bf[nb2 * 2 + 1][1] = rg[3];
            }
#pragma unroll
            for (int mb = 0; mb < 4; mb++)
#pragma unroll
                for (int nb = 0; nb < 4; nb++)
                    mma16816h(acc[mb][nb], Af[mb], Bf[nb]);
        }
        __syncthreads();
    }

#pragma unroll
    for (int mb = 0; mb < 4; mb++) {
        const int r = mBase + wm * 64 + mb * 16 + (lane >> 2);
#pragma unroll
        for (int nb = 0; nb < 4; nb++) {
            const int cc = wn * 32 + nb * 8 + (lane & 3) * 2;
            float v0 = acc[mb][nb][0], v1 = acc[mb][nb][1];
            float v2 = acc[mb][nb][2], v3 = acc[mb][nb][3];
            __half h0 = __float2half_rn(v0), h1 = __float2half_rn(v1);
            __half h2 = __float2half_rn(v2), h3 = __float2half_rn(v3);
            if (!isV) {
                *(__half2*)&Op[(long)r * ldc + cc] = __halves2half2(h0, h1);
                *(__half2*)&Op[(long)(r + 8) * ldc + cc] = __halves2half2(h2, h3);
            } else {
                Op[(long)cc * ldc + r] = h0;
                Op[(long)(cc + 1) * ldc + r] = h1;
                Op[(long)cc * ldc + r + 8] = h2;
                Op[(long)(cc + 1) * ldc + r + 8] = h3;
            }
        }
    }
}

// ---------------- fp16 flash attention: S 1-term, PV 1-term -------------------
// FLASH_SMEM padded above 114 KB so 2 CTAs cannot co-reside: pins 1 CTA/SM,
// reproducing the R13 execution configuration (eliminates the occupancy flip).
#define FQ_S 136
#define FV_S 72
#define FQ_O 0
#define FK_O 17408             // + stage*8704 (K single plane)
#define FV_O 34816             // + stage*9216 (V single plane)
#define FLASH_SMEM 120832      // used: 106496; padded to force 1 CTA/SM
#define SCALE_F 0.08838834764831845f

__global__ __launch_bounds__(256)
void flash_tc(const __half* __restrict__ Q,
              const __half* __restrict__ K,
              const __half* __restrict__ Vt,
              __half* __restrict__ AO)
{
    extern __shared__ __half fsm[];
    const int qt = (int)gridDim.x - 1 - (int)blockIdx.x;   // LPT
    const int h = blockIdx.y, b = blockIdx.z;
    const int tid = threadIdx.x, lane = tid & 31, w = tid >> 5;
    const float slope = exp2f(-0.5f * (float)(h + 1));
    const int nt = 2 * qt + 2;

    const uint32_t fb = su(fsm);

    {
        const int r = tid >> 1, cb = (tid & 1) * 64;
        const __half* sq = Q + (long)(b * 2048 + qt * 128 + r) * 2048 + h * 128 + cb;
        const uint32_t dq = fb + (FQ_O + r * FQ_S + cb) * 2;
#pragma unroll
        for (int u = 0; u < 8; u++) cpa16(dq + u * 16, sq + u * 8);
    }
    auto loadKV = [&](int stg, int jt) {
        const int kr = tid >> 2, kcb = (tid & 3) * 32;
        const long krow = (long)h * 4096 + b * 2048 + jt * 64 + kr;
        const __half* sk = K + krow * 128 + kcb;
        const uint32_t kd = fb + (FK_O + stg * 8704 + kr * FQ_S + kcb) * 2;
#pragma unroll
        for (int u = 0; u < 4; u++) cpa16(kd + u * 16, sk + u * 8);
        const int vr = tid >> 1, vcb = (tid & 1) * 32;
        const long vrow = (long)h * 128 + vr;
        const __half* sv = Vt + vrow * 4096 + b * 2048 + jt * 64 + vcb;
        const uint32_t vd = fb + (FV_O + stg * 9216 + vr * FV_S + vcb) * 2;
#pragma unroll
        for (int u = 0; u < 4; u++) cpa16(vd + u * 16, sv + u * 8);
    };
    loadKV(0, 0);
    asm volatile("cp.async.commit_group;");

    const int aRow = w * 16 + (lane & 15);
    const int aCol8 = (lane >> 4) << 3;
    const int bRow8 = ((lane >> 4) << 3) + (lane & 7);
    const int bCol8 = ((lane >> 3) & 1) << 3;

    float m0 = -1e30f, m1 = -1e30f, l0 = 0.f, l1 = 0.f;
    float o[16][4];
#pragma unroll
    for (int i = 0; i < 16; i++)
#pragma unroll
        for (int j = 0; j < 4; j++) o[i][j] = 0.f;

    const int grow0 = qt * 128 + w * 16 + (lane >> 2);

    for (int jt = 0; jt < nt; jt++) {
        const int cur = jt & 1;
        if (jt > 0) __syncthreads();
        if (jt + 1 < nt) {
            loadKV(cur ^ 1, jt + 1);
            asm volatile("cp.async.commit_group;");
            asm volatile("cp.async.wait_group 1;");
        } else {
            asm volatile("cp.async.wait_group 0;");
        }
        __syncthreads();

        const uint32_t bK = fb + (FK_O + cur * 8704) * 2;
        const uint32_t bV = fb + (FV_O + cur * 9216) * 2;

        float s[8][4];
#pragma unroll
        for (int i = 0; i < 8; i++)
#pragma unroll
            for (int j = 0; j < 4; j++) s[i][j] = 0.f;

#pragma unroll
        for (int ks = 0; ks < 8; ks++) {
            uint32_t qf[4];
            const uint32_t aoff = (uint32_t)(aRow * FQ_S + ks * 16 + aCol8) * 2;
            ldsm4(qf, fb + FQ_O * 2 + aoff);
#pragma unroll
            for (int nb2 = 0; nb2 < 4; nb2++) {
                const uint32_t boff = (uint32_t)((nb2 * 16 + bRow8) * FQ_S + ks * 16 + bCol8) * 2;
                uint32_t kk[4];
                ldsm4(kk, bK + boff);
                mma16816h(s[2 * nb2],     qf, &kk[0]);
                mma16816h(s[2 * nb2 + 1], qf, &kk[2]);
            }
        }

#pragma unroll
        for (int nb = 0; nb < 8; nb++) {
#pragma unroll
            for (int j = 0; j < 2; j++) {
                const int gc = jt * 64 + nb * 8 + (lane & 3) * 2 + j;
                float v = s[nb][j];
                s[nb][j] = (gc > grow0) ? -1e30f
                          : v * SCALE_F - slope * (float)(grow0 - gc);
                float v2 = s[nb][2 + j];
                s[nb][2 + j] = (gc > grow0 + 8) ? -1e30f
                          : v2 * SCALE_F - slope * (float)(grow0 + 8 - gc);
            }
        }

        float mx0 = -1e30f, mx1 = -1e30f;
#pragma unroll
        for (int nb = 0; nb < 8; nb++) {
            mx0 = fmaxf(mx0, fmaxf(s[nb][0], s[nb][1]));
            mx1 = fmaxf(mx1, fmaxf(s[nb][2], s[nb][3]));
        }
        mx0 = fmaxf(mx0, __shfl_xor_sync(0xffffffffu, mx0, 1));
        mx0 = fmaxf(mx0, __shfl_xor_sync(0xffffffffu, mx0, 2));
        mx1 = fmaxf(mx1, __shfl_xor_sync(0xffffffffu, mx1, 1));
        mx1 = fmaxf(mx1, __shfl_xor_sync(0xffffffffu, mx1, 2));
        const float mn0 = fmaxf(m0, mx0), mn1 = fmaxf(m1, mx1);
        const float al0 = __expf(m0 - mn0), al1 = __expf(m1 - mn1);
        m0 = mn0; m1 = mn1;

        float sum0 = 0.f, sum1 = 0.f;
#pragma unroll
        for (int nb = 0; nb < 8; nb++) {
            s[nb][0] = __half2float(__float2half_rn(__expf(s[nb][0] - mn0))); sum0 += s[nb][0];
            s[nb][1] = __half2float(__float2half_rn(__expf(s[nb][1] - mn0))); sum0 += s[nb][1];
            s[nb][2] = __half2float(__float2half_rn(__expf(s[nb][2] - mn1))); sum1 += s[nb][2];
            s[nb][3] = __half2float(__float2half_rn(__expf(s[nb][3] - mn1))); sum1 += s[nb][3];
        }
        sum0 += __shfl_xor_sync(0xffffffffu, sum0, 1);
        sum0 += __shfl_xor_sync(0xffffffffu, sum0, 2);
        sum1 += __shfl_xor_sync(0xffffffffu, sum1, 1);
        sum1 += __shfl_xor_sync(0xffffffffu, sum1, 2);
        l0 = l0 * al0 + sum0;
        l1 = l1 * al1 + sum1;

#pragma unroll
        for (int nb = 0; nb < 16; nb++) {
            o[nb][0] *= al0; o[nb][1] *= al0;
            o[nb][2] *= al1; o[nb][3] *= al1;
        }

        uint32_t ph[4][4];
#pragma unroll
        for (int kb = 0; kb < 4; kb++) {
#pragma unroll
            for (int q = 0; q < 4; q++) {
                const float x = s[2 * kb + (q >> 1)][(q & 1) * 2 + 0];
                const float y = s[2 * kb + (q >> 1)][(q & 1) * 2 + 1];
                ph[kb][q] = pack2h(__float2half_rn(x), __float2half_rn(y));
            }
        }

#pragma unroll
        for (int kb = 0; kb < 4; kb++) {
#pragma unroll
            for (int nb2 = 0; nb2 < 8; nb2++) {
                const uint32_t voff = (uint32_t)((nb2 * 16 + bRow8) * FV_S + kb * 16 + bCol8) * 2;
                uint32_t vv[4];
                ldsm4(vv, bV + voff);
                mma16816h(o[2 * nb2],     ph[kb], &vv[0]);
                mma16816h(o[2 * nb2 + 1], ph[kb], &vv[2]);
            }
        }
    }

    const float inv0 = 1.f / l0, inv1 = 1.f / l1;
    const long row0 = (long)b * 2048 + qt * 128 + w * 16 + (lane >> 2);
#pragma unroll
    for (int nb = 0; nb < 16; nb++) {
        const int c = h * 128 + nb * 8 + (lane & 3) * 2;
        *(__half2*)&AO[row0 * 2048 + c] =
            __halves2half2(__float2half_rn(o[nb][0] * inv0), __float2half_rn(o[nb][1] * inv0));
        *(__half2*)&AO[(row0 + 8) * 2048 + c] =
            __halves2half2(__float2half_rn(o[nb][2] * inv1), __float2half_rn(o[nb][3] * inv1));
    }
}

// ---------------- launch ------------------------------------------------------
extern "C" void kernel_launch(void* const* d_in, const int* in_sizes, int n_in,
                              void* d_out, int out_size)
{
    const float* X    = (const float*)d_in[0];
    const float* Wqd  = (const float*)d_in[1];
    const float* Wqu  = (const float*)d_in[2];
    const float* Wkvd = (const float*)d_in[3];
    const float* kup  = (const float*)d_in[4];
    const float* vup  = (const float*)d_in[5];
    const float* Wo   = (const float*)d_in[6];
    float* out = (float*)d_out;

    __half *x, *xq, *cb, *q, *k, *vt, *ao;
    cudaGetSymbolAddress((void**)&x, g_X);
    cudaGetSymbolAddress((void**)&xq, g_Xq);
    cudaGetSymbolAddress((void**)&cb, g_Cb);
    cudaGetSymbolAddress((void**)&q, g_Q);
    cudaGetSymbolAddress((void**)&k, g_K);
    cudaGetSymbolAddress((void**)&vt, g_Vt);
    cudaGetSymbolAddress((void**)&ao, g_AO);

    __half *wqd, *wqu, *wkvd, *wo, *ku, *vu;
    cudaGetSymbolAddress((void**)&wqd, g_Wqd);
    cudaGetSymbolAddress((void**)&wqu, g_Wqu);
    cudaGetSymbolAddress((void**)&wkvd, g_Wkvd);
    cudaGetSymbolAddress((void**)&wo, g_Wo);
    cudaGetSymbolAddress((void**)&ku, g_kupT);
    cudaGetSymbolAddress((void**)&vu, g_vupT);

    cudaFuncSetAttribute(gemm_tc<0>, cudaFuncAttributeMaxDynamicSharedMemorySize, GEMM_SMEM);
    cudaFuncSetAttribute(gemm_tc<1>, cudaFuncAttributeMaxDynamicSharedMemorySize, GEMM_SMEM);
    cudaFuncSetAttribute(gemm_kv, cudaFuncAttributeMaxDynamicSharedMemorySize, GEMM_SMEM);
    cudaFuncSetAttribute(flash_tc, cudaFuncAttributeMaxDynamicSharedMemorySize, FLASH_SMEM);

    // ---- prep: single fp16 planes everywhere ----
    conv_single4<<<(4096 * 2048 / 4 + 255) / 256, 256>>>(X, x, 4096 * 2048 / 4);
    conv_single4<<<(1536 * 2048 / 4 + 255) / 256, 256>>>(Wqd, wqd, 1536 * 2048 / 4);
    conv_single4<<<(2048 * 1536 / 4 + 255) / 256, 256>>>(Wqu, wqu, 2048 * 1536 / 4);
    conv_single4<<<(512 * 2048 / 4 + 255) / 256, 256>>>(Wkvd, wkvd, 512 * 2048 / 4);
    conv_single4<<<(2048 * 2048 / 4 + 255) / 256, 256>>>(Wo, wo, 2048 * 2048 / 4);
    conv_transpose1<<<(16 * 512 * 128 + 255) / 256, 256>>>(kup, ku, 16, 512, 128);
    conv_transpose1<<<(16 * 512 * 128 + 255) / 256, 256>>>(vup, vu, 16, 512, 128);

    // 1) [Xq | C] = X @ [Wqd | Wkvd]^T  (merged-N)
    gemm_tc<1><<<dim3(16, 32), 256, GEMM_SMEM>>>(x, wqd, nullptr, xq,
        4096, 2048, 2048, 2048, 1536,
        wkvd, cb, 1536, 512);
    // 2) Q = Xq @ Wq_up^T
    gemm_tc<1><<<dim3(16, 32), 256, GEMM_SMEM>>>(xq, wqu, nullptr, q,
        4096, 2048, 1536, 1536, 2048,
        nullptr, nullptr, 1 << 30, 0);
    // 3) fused K/V up-projections (both single plane; V transposed)
    gemm_kv<<<1024, 256, GEMM_SMEM>>>(cb, ku, k, vu, vt);
    // 4) attention (LPT; S and PV both 1-term; 1 CTA/SM pinned via smem pad)
    flash_tc<<<dim3(16, 16, 2), 256, FLASH_SMEM>>>(q, k, vt, ao);
    // 5) out = AO @ Wo^T (fp32)
    gemm_tc<0><<<dim3(16, 32), 256, GEMM_SMEM>>>(ao, wo, out, nullptr,
        4096, 2048, 2048, 2048, 2048,
        nullptr, nullptr, 1 << 30, 0);
}